// round 13
// baseline (speedup 1.0000x reference)
#include <cuda_runtime.h>
#include <cuda_bf16.h>
#include <cuda_fp16.h>

// ---------------------------------------------------------------------------
// R13: R12 regressed (189us) from register spills: (128,7) cap 73 vs true
// demand ~85 -> ~18MB local traffic (L2 38%, HBM 310GB/s). Fix: keep S in
// REGISTERS (no LDS in flow critical path) and cut genuine pressure instead:
//  1. NC 12 -> 8 everywhere: co[] 24 -> 16 regs, gamma -4 pfma/eval,
//     lerp 2x float4/row. Natural demand ~86.
//  2. __launch_bounds__(128,6) -> cap 85, 24 warps/SM (+20% issue capacity),
//     squeeze of ~1-3 regs (not R12's 12+).
//  3. Keep f16 chain-combine (3 HADD2 + one cvt) from R11 -- it was innocent.
//  4. Shooting keeps clamps (low-metric regions can sustain |Gamma|~0.5 ->
//     trajectories can escape [-1,2]; clamps are load-bearing).
// ---------------------------------------------------------------------------

#define NC      8
#define GL      512
#define C_MIN   (-1.0f)
#define C_MAX   (2.0f)
#define C_MID   (0.5f)
#define C_HALF  (1.5f)
#define C_INVH  (0.66666666666666667f)
#define C_MOFF  (-0.33333333333333333f)
#define PI_F    3.14159265358979323846f
#define FD_EPS_F 1e-4f

typedef unsigned long long u64;
typedef unsigned int u32;

__device__ float g_coef[GL * NC];

// packed f32x2 helpers ------------------------------------------------------
__device__ __forceinline__ u64 pk(float lo, float hi) {
    u64 r; asm("mov.b64 %0, {%1, %2};" : "=l"(r) : "f"(lo), "f"(hi)); return r;
}
__device__ __forceinline__ void upk(u64 a, float& x, float& y) {
    asm("mov.b64 {%0, %1}, %2;" : "=f"(x), "=f"(y) : "l"(a));
}
__device__ __forceinline__ u64 pfma(u64 a, u64 b, u64 c) {
    u64 d; asm("fma.rn.f32x2 %0, %1, %2, %3;" : "=l"(d) : "l"(a), "l"(b), "l"(c)); return d;
}
__device__ __forceinline__ u64 pmul(u64 a, u64 b) {
    u64 d; asm("mul.rn.f32x2 %0, %1, %2;" : "=l"(d) : "l"(a), "l"(b)); return d;
}
__device__ __forceinline__ u64 padd(u64 a, u64 b) {
    u64 d; asm("add.rn.f32x2 %0, %1, %2;" : "=l"(d) : "l"(a), "l"(b)); return d;
}
// f32x2 (u64) -> f16x2 (b32), lane-preserving: lo->lo, hi->hi
__device__ __forceinline__ u32 cvt_h2(u64 p) {
    float x, y; upk(p, x, y);
    u32 r; asm("cvt.rn.f16x2.f32 %0, %1, %2;" : "=r"(r) : "f"(y), "f"(x));
    return r;   // first src -> hi half
}
__device__ __forceinline__ u32 tanh_h2(u32 h) {
    u32 r; asm("tanh.approx.f16x2 %0, %1;" : "=r"(r) : "r"(h)); return r;
}
__device__ __forceinline__ u32 hfma2(u32 a, u32 b, u32 c) {
    u32 d; asm("fma.rn.f16x2 %0, %1, %2, %3;" : "=r"(d) : "r"(a), "r"(b), "r"(c)); return d;
}
__device__ __forceinline__ u32 hadd2(u32 a, u32 b) {
    u32 d; asm("add.rn.f16x2 %0, %1, %2;" : "=r"(d) : "r"(a), "r"(b)); return d;
}
// f16x2 -> f32x2 (lane-preserving)
__device__ __forceinline__ u64 h2_to_p(u32 h) {
    unsigned short lo, hi;
    asm("mov.b32 {%0, %1}, %2;" : "=h"(lo), "=h"(hi) : "r"(h));
    float fl, fh;
    asm("cvt.f32.f16 %0, %1;" : "=f"(fl) : "h"(lo));
    asm("cvt.f32.f16 %0, %1;" : "=f"(fh) : "h"(hi));
    return pk(fl, fh);
}
__device__ __forceinline__ u32 f2h2(float v) {   // broadcast f32 -> f16x2
    u32 r; asm("cvt.rn.f16x2.f32 %0, %1, %1;" : "=r"(r) : "f"(v));
    return r;
}

#define PK_M1    0xBF800000BF800000ULL   // (-1, -1)
#define PK_DT    0x3DCCCCCD3DCCCCCDULL   // (0.1, 0.1)
#define PK_NDT   0xBDCCCCCDBDCCCCCDULL   // (-0.1, -0.1)
#define PK_INVH  0x3F2AAAAB3F2AAAABULL   // ( 2/3,  2/3)
#define PK_MOFF  0xBEAAAAABBEAAAAABULL   // (-1/3, -1/3)

// ----------------------------- precompute ----------------------------------

__device__ __forceinline__ float metric_eval(
    float c, float lam,
    const float* __restrict__ mW1, const float* __restrict__ mb1,
    const float* __restrict__ mW2, const float* __restrict__ mb2,
    const float* __restrict__ mW3, const float* __restrict__ mb3)
{
    float h1[8];
#pragma unroll
    for (int j = 0; j < 8; j++)
        h1[j] = tanhf(fmaf(c, mW1[j], fmaf(lam, mW1[8 + j], mb1[j])));
    float h2[8];
#pragma unroll
    for (int j = 0; j < 8; j++) {
        float p = mb2[j];
#pragma unroll
        for (int k = 0; k < 8; k++) p = fmaf(h1[k], mW2[k * 8 + j], p);
        h2[j] = tanhf(p);
    }
    float o = mb3[0];
#pragma unroll
    for (int k = 0; k < 8; k++) o = fmaf(h2[k], mW3[k], o);
    float sp = (o > 20.0f) ? o : log1pf(expf(o));
    return sp + 1e-6f;
}

// Fused: Gamma at Chebyshev nodes (smem) -> DCT -> g_coef.
#define ROWS_PER_BLK 16
__global__ void precompute_kernel(
    const float* __restrict__ mW1, const float* __restrict__ mb1,
    const float* __restrict__ mW2, const float* __restrict__ mb2,
    const float* __restrict__ mW3, const float* __restrict__ mb3)
{
    __shared__ float nodes[ROWS_PER_BLK][NC];
    int t = threadIdx.x;
    int r = t / NC;
    int k = t - r * NC;
    int lrow = blockIdx.x * ROWS_PER_BLK + r;

    if (r < ROWS_PER_BLK && lrow < GL) {
        float lam = (float)lrow * (1.0f / (GL - 1));
        float th = (k + 0.5f) * (PI_F / NC);
        float c  = C_MID + C_HALF * __cosf(th);
        float g0 = metric_eval(c,            lam, mW1, mb1, mW2, mb2, mW3, mb3);
        float gp = metric_eval(c + FD_EPS_F, lam, mW1, mb1, mW2, mb2, mW3, mb3);
        float gm = metric_eval(c - FD_EPS_F, lam, mW1, mb1, mW2, mb2, mW3, mb3);
        float dg = (gp - gm) * (1.0f / (2.0f * FD_EPS_F));
        nodes[r][k] = 0.5f * dg / g0;
    }
    __syncthreads();
    if (r < ROWS_PER_BLK && lrow < GL) {
        int j = k;
        float s = 0.0f;
#pragma unroll
        for (int q = 0; q < NC; q++)
            s += nodes[r][q] * __cosf((PI_F / NC) * (float)j * ((float)q + 0.5f));
        s *= (j == 0) ? (1.0f / NC) : (2.0f / NC);
        g_coef[lrow * NC + j] = s;
    }
}

// ----------------------------- main kernel ---------------------------------

// Even/odd split Clenshaw (two independent 4-term chains).
template<bool CLAMP>
__device__ __forceinline__ u64 eval_gamma_eo(const u64 co[NC], u64 C)
{
    u64 T;
    if (CLAMP) {
        float cx, cy; upk(C, cx, cy);
        cx = fminf(fmaxf(cx, C_MIN), C_MAX);
        cy = fminf(fmaxf(cy, C_MIN), C_MAX);
        T = pk(fmaf(cx, (float)C_INVH, (float)C_MOFF),
               fmaf(cy, (float)C_INVH, (float)C_MOFF));
    } else {
        T = pfma(C, PK_INVH, PK_MOFF);
    }
    u64 U  = pfma(padd(T, T), T, PK_M1);     // u = 2t^2 - 1
    u64 U2 = padd(U, U);

    const int H = NC / 2;   // 4 per chain
    u64 be1 = 0ull, be2 = 0ull;   // even chain (T-basis over u)
    u64 bo1 = 0ull, bo2 = 0ull;   // odd chain  (V-basis over u)
#pragma unroll
    for (int k = H - 1; k >= 1; k--) {
        u64 de = pfma(be2, PK_M1, co[2 * k]);
        u64 be = pfma(U2, be1, de);
        be2 = be1; be1 = be;
        u64 dd = pfma(bo2, PK_M1, co[2 * k + 1]);
        u64 bo = pfma(U2, bo1, dd);
        bo2 = bo1; bo1 = bo;
    }
    u64 pe = pfma(U, be1, pfma(be2, PK_M1, co[0]));       // e0 - be2 + u*be1
    u64 b0 = pfma(U2, bo1, pfma(bo2, PK_M1, co[1]));      // o0 + 2u*bo1 - bo2
    u64 dv = pfma(bo1, PK_M1, b0);                        // b0 - bo1
    return pfma(T, dv, pe);
}

// Euler c-endpoint: 9 full steps + 1 drift step (last Gamma is dead code).
__device__ __forceinline__ u64 integrate_c(const u64 co[NC], u64 C0, u64 V0)
{
    u64 C = C0, V = V0;
#pragma unroll 1
    for (int s = 0; s < 9; s++) {
        u64 G   = eval_gamma_eo<true>(co, C);
        u64 Cn  = pfma(V, PK_DT, C);
        u64 gv  = pmul(G, V);
        u64 gvv = pmul(gv, V);
        V = pfma(gvv, PK_NDT, V);
        C = Cn;
    }
    return pfma(V, PK_DT, C);
}

// All 10 reference shooting iterations in closed form from ONE integration.
__device__ __forceinline__ float shoot_single(float c0, float v0,
                                              float F0, float ctg)
{
    float Teff = __fdividef(F0 - c0, v0);
    float b    = 2.0f * Teff - 1.0f;
    bool ok    = (fabsf(v0) > 1e-7f) && (fabsf(b) > 0.1f);
    b = ok ? b : 1.0f;
    float vs = v0 + __fdividef(ctg - F0, b);
    float r  = 1.0f - 0.5f * b;
    float r2 = r * r, r4 = r2 * r2, r8 = r4 * r4, r10 = r8 * r2;
    return fmaf(r10, v0 - vs, vs);
}

__global__ __launch_bounds__(128, 6)
void geodesic_main_kernel(
    const float* __restrict__ c_src, const float* __restrict__ c_tgt,
    const float* __restrict__ lamv,  const float* __restrict__ A_src,
    const float* __restrict__ sW1,   const float* __restrict__ sb1,
    const float* __restrict__ sW2,   const float* __restrict__ sb2,
    float* __restrict__ out, int n)
{
    __shared__ ulonglong2 Wab[16];    // {pk(cw,cw), pk(vw,vw)}
    __shared__ ulonglong2 Wcd[16];    // {pk(aw,aw), (u64)f16x2(w2,w2)}
    __shared__ float shC[16], shB1[16];
    __shared__ float shT2;

    int t = threadIdx.x;
    if (t < 16) {
        int j = t;
        float a  = sW1[j];
        float b  = sW1[16 + j];
        float cw = sW1[32 + j];
        float dw = sW1[48 + j];
        float w2 = sW2[j];
        Wab[j] = make_ulonglong2(pk(a, a), pk(b, b));
        Wcd[j] = make_ulonglong2(pk(dw, dw), (u64)f2h2(w2));
        shC[j]  = cw;
        shB1[j] = sb1[j];
    } else if (t == 16) {
        shT2 = sb2[0];
    }
    __syncthreads();

    int half = (n + 1) >> 1;
    int i = blockIdx.x * 128 + t;
    if (i >= half) return;
    int i2 = i + half;
    bool has2 = (i2 < n);
    int j2 = has2 ? i2 : i;

    float c0x = c_src[i],  c0y = c_src[j2];
    float ctx = c_tgt[i],  cty = c_tgt[j2];
    float lmx = lamv[i],   lmy = lamv[j2];
    float a0x = A_src[i],  a0y = A_src[j2];

    // --- lambda-lerp of Chebyshev rows, packed (NC=8: 2 float4 per row) ---
    float yx = fminf(fmaxf(lmx * (float)(GL - 1), 0.0f), (float)(GL - 1));
    float yy = fminf(fmaxf(lmy * (float)(GL - 1), 0.0f), (float)(GL - 1));
    int lx = min((int)yx, GL - 2);
    int ly = min((int)yy, GL - 2);
    float fx = yx - (float)lx;
    float fy = yy - (float)ly;

    const float4* rx0 = (const float4*)(g_coef + lx * NC);
    const float4* rx1 = (const float4*)(g_coef + (lx + 1) * NC);
    const float4* ry0 = (const float4*)(g_coef + ly * NC);
    const float4* ry1 = (const float4*)(g_coef + (ly + 1) * NC);

    u64 co[NC];
#pragma unroll
    for (int q = 0; q < NC / 4; q++) {
        float4 ax = __ldg(rx0 + q), bx = __ldg(rx1 + q);
        float4 ay = __ldg(ry0 + q), by = __ldg(ry1 + q);
        co[4*q+0] = pk(fmaf(fx, bx.x - ax.x, ax.x), fmaf(fy, by.x - ay.x, ay.x));
        co[4*q+1] = pk(fmaf(fx, bx.y - ax.y, ax.y), fmaf(fy, by.y - ay.y, ay.y));
        co[4*q+2] = pk(fmaf(fx, bx.z - ax.z, ax.z), fmaf(fy, by.z - ay.z, ay.z));
        co[4*q+3] = pk(fmaf(fx, bx.w - ax.w, ax.w), fmaf(fy, by.w - ay.w, ay.w));
    }

    // --- per-element static flow terms S_j = b1_j + lam*W1c_j (registers) ---
    u64 S[16];
#pragma unroll
    for (int j = 0; j < 16; j++)
        S[j] = pk(fmaf(lmx, shC[j], shB1[j]), fmaf(lmy, shC[j], shB1[j]));

    // --- shooting: ONE truncated integration + derivative-model tail ---
    u64 C0p = pk(c0x, c0y);
    float v0x = ctx - c0x, v0y = cty - c0y;
    u64 F0p = integrate_c(co, C0p, pk(v0x, v0y));
    float F0x, F0y; upk(F0p, F0x, F0y);

    float vx = shoot_single(c0x, v0x, F0x, ctx);
    float vy = shoot_single(c0y, v0y, F0y, cty);

    // --- final integrate with spectral flow (no clamps: solved trajectory) ---
    u64 C = C0p, V = pk(vx, vy), A = pk(a0x, a0y);
    u64 T2p = pk(shT2, shT2);
#pragma unroll 1
    for (int s = 0; s < 10; s++) {
        u32 h0 = 0u, h1 = 0u, h2 = 0u, h3 = 0u;   // 4 indep f16x2 chains
#pragma unroll
        for (int j = 0; j < 16; j += 4) {
#pragma unroll
            for (int q = 0; q < 4; q++) {
                ulonglong2 wab = Wab[j + q];
                ulonglong2 wcd = Wcd[j + q];
                u64 pre = pfma(C, wab.x, S[j + q]);
                pre = pfma(V, wab.y, pre);
                pre = pfma(A, wcd.x, pre);
                u32 th = tanh_h2(cvt_h2(pre));
                u32 w2h = (u32)wcd.y;
                if (q == 0)      h0 = hfma2(th, w2h, h0);
                else if (q == 1) h1 = hfma2(th, w2h, h1);
                else if (q == 2) h2 = hfma2(th, w2h, h2);
                else             h3 = hfma2(th, w2h, h3);
            }
        }
        // combine chains in f16, ONE conversion to f32
        u32 hs = hadd2(hadd2(h0, h1), hadd2(h2, h3));
        u64 acc = padd(h2_to_p(hs), T2p);
        if (s < 9) {
            u64 G = eval_gamma_eo<false>(co, C);
            u64 Cn  = pfma(V, PK_DT, C);
            u64 gv  = pmul(G, V);
            u64 gvv = pmul(gv, V);
            V = pfma(gvv, PK_NDT, V);
            A = pfma(acc, PK_DT, A);
            C = Cn;
        } else {
            A = pfma(acc, PK_DT, A);   // last step: c/v updates are dead
        }
    }

    float Ax, Ay; upk(A, Ax, Ay);
    out[i] = Ax;
    if (has2) out[i2] = Ay;
}

// ----------------------------- launcher ------------------------------------

extern "C" void kernel_launch(void* const* d_in, const int* in_sizes, int n_in,
                              void* d_out, int out_size)
{
    const float* c_src = (const float*)d_in[0];
    const float* c_tgt = (const float*)d_in[1];
    const float* lam   = (const float*)d_in[2];
    const float* A_src = (const float*)d_in[3];
    const float* mW1 = (const float*)d_in[4];
    const float* mb1 = (const float*)d_in[5];
    const float* mW2 = (const float*)d_in[6];
    const float* mb2 = (const float*)d_in[7];
    const float* mW3 = (const float*)d_in[8];
    const float* mb3 = (const float*)d_in[9];
    const float* sW1 = (const float*)d_in[10];
    const float* sb1 = (const float*)d_in[11];
    const float* sW2 = (const float*)d_in[12];
    const float* sb2 = (const float*)d_in[13];

    int n = in_sizes[0];

    int pre_blocks = (GL + ROWS_PER_BLK - 1) / ROWS_PER_BLK;
    precompute_kernel<<<pre_blocks, ROWS_PER_BLK * NC>>>(mW1, mb1, mW2, mb2, mW3, mb3);

    int half = (n + 1) / 2;
    int blocks = (half + 127) / 128;
    geodesic_main_kernel<<<blocks, 128>>>(c_src, c_tgt, lam, A_src,
                                          sW1, sb1, sW2, sb2,
                                          (float*)d_out, n);
}

// round 14
// speedup vs baseline: 1.6998x; 1.6998x over previous
#include <cuda_runtime.h>
#include <cuda_bf16.h>
#include <cuda_fp16.h>

// ---------------------------------------------------------------------------
// R14: R12+R13 established: ANY launch_bounds cap below natural reg demand
// loses (spill at -12, remat/MOV bloat at -5). Occupancy lever is closed.
// R14 = R10's exact launch shape (128,5 / cap 102, natural alloc, 20 warps)
// plus only the cap-free work cuts validated since:
//  * NC=8 gamma table (R13 numerics: rel_err 4.9e-4) -> -76 FFMA2 in gamma,
//    half the lerp loads, -8 regs (natural ~88, never capped)
//  * f16 chain-combine from R11 (3 HADD2 + one cvt, -70 issues)
// Frozen: tanh.approx.f16x2 flow, single-integration shooting + drag-model
// affine tail, even/odd Clenshaw, f32x2 packing, 2 elem/thread.
// ---------------------------------------------------------------------------

#define NC      8
#define GL      512
#define C_MIN   (-1.0f)
#define C_MAX   (2.0f)
#define C_MID   (0.5f)
#define C_HALF  (1.5f)
#define C_INVH  (0.66666666666666667f)
#define C_MOFF  (-0.33333333333333333f)
#define PI_F    3.14159265358979323846f
#define FD_EPS_F 1e-4f

typedef unsigned long long u64;
typedef unsigned int u32;

__device__ float g_coef[GL * NC];

// packed f32x2 helpers ------------------------------------------------------
__device__ __forceinline__ u64 pk(float lo, float hi) {
    u64 r; asm("mov.b64 %0, {%1, %2};" : "=l"(r) : "f"(lo), "f"(hi)); return r;
}
__device__ __forceinline__ void upk(u64 a, float& x, float& y) {
    asm("mov.b64 {%0, %1}, %2;" : "=f"(x), "=f"(y) : "l"(a));
}
__device__ __forceinline__ u64 pfma(u64 a, u64 b, u64 c) {
    u64 d; asm("fma.rn.f32x2 %0, %1, %2, %3;" : "=l"(d) : "l"(a), "l"(b), "l"(c)); return d;
}
__device__ __forceinline__ u64 pmul(u64 a, u64 b) {
    u64 d; asm("mul.rn.f32x2 %0, %1, %2;" : "=l"(d) : "l"(a), "l"(b)); return d;
}
__device__ __forceinline__ u64 padd(u64 a, u64 b) {
    u64 d; asm("add.rn.f32x2 %0, %1, %2;" : "=l"(d) : "l"(a), "l"(b)); return d;
}
// f32x2 (u64) -> f16x2 (b32), lane-preserving: lo->lo, hi->hi
__device__ __forceinline__ u32 cvt_h2(u64 p) {
    float x, y; upk(p, x, y);
    u32 r; asm("cvt.rn.f16x2.f32 %0, %1, %2;" : "=r"(r) : "f"(y), "f"(x));
    return r;   // first src -> hi half
}
__device__ __forceinline__ u32 tanh_h2(u32 h) {
    u32 r; asm("tanh.approx.f16x2 %0, %1;" : "=r"(r) : "r"(h)); return r;
}
__device__ __forceinline__ u32 hfma2(u32 a, u32 b, u32 c) {
    u32 d; asm("fma.rn.f16x2 %0, %1, %2, %3;" : "=r"(d) : "r"(a), "r"(b), "r"(c)); return d;
}
__device__ __forceinline__ u32 hadd2(u32 a, u32 b) {
    u32 d; asm("add.rn.f16x2 %0, %1, %2;" : "=r"(d) : "r"(a), "r"(b)); return d;
}
// f16x2 -> f32x2 (lane-preserving)
__device__ __forceinline__ u64 h2_to_p(u32 h) {
    unsigned short lo, hi;
    asm("mov.b32 {%0, %1}, %2;" : "=h"(lo), "=h"(hi) : "r"(h));
    float fl, fh;
    asm("cvt.f32.f16 %0, %1;" : "=f"(fl) : "h"(lo));
    asm("cvt.f32.f16 %0, %1;" : "=f"(fh) : "h"(hi));
    return pk(fl, fh);
}
__device__ __forceinline__ u32 f2h2(float v) {   // broadcast f32 -> f16x2
    u32 r; asm("cvt.rn.f16x2.f32 %0, %1, %1;" : "=r"(r) : "f"(v));
    return r;
}

#define PK_M1    0xBF800000BF800000ULL   // (-1, -1)
#define PK_DT    0x3DCCCCCD3DCCCCCDULL   // (0.1, 0.1)
#define PK_NDT   0xBDCCCCCDBDCCCCCDULL   // (-0.1, -0.1)
#define PK_INVH  0x3F2AAAAB3F2AAAABULL   // ( 2/3,  2/3)
#define PK_MOFF  0xBEAAAAABBEAAAAABULL   // (-1/3, -1/3)

// ----------------------------- precompute ----------------------------------

__device__ __forceinline__ float metric_eval(
    float c, float lam,
    const float* __restrict__ mW1, const float* __restrict__ mb1,
    const float* __restrict__ mW2, const float* __restrict__ mb2,
    const float* __restrict__ mW3, const float* __restrict__ mb3)
{
    float h1[8];
#pragma unroll
    for (int j = 0; j < 8; j++)
        h1[j] = tanhf(fmaf(c, mW1[j], fmaf(lam, mW1[8 + j], mb1[j])));
    float h2[8];
#pragma unroll
    for (int j = 0; j < 8; j++) {
        float p = mb2[j];
#pragma unroll
        for (int k = 0; k < 8; k++) p = fmaf(h1[k], mW2[k * 8 + j], p);
        h2[j] = tanhf(p);
    }
    float o = mb3[0];
#pragma unroll
    for (int k = 0; k < 8; k++) o = fmaf(h2[k], mW3[k], o);
    float sp = (o > 20.0f) ? o : log1pf(expf(o));
    return sp + 1e-6f;
}

// Fused: Gamma at Chebyshev nodes (smem) -> DCT -> g_coef.
#define ROWS_PER_BLK 16
__global__ void precompute_kernel(
    const float* __restrict__ mW1, const float* __restrict__ mb1,
    const float* __restrict__ mW2, const float* __restrict__ mb2,
    const float* __restrict__ mW3, const float* __restrict__ mb3)
{
    __shared__ float nodes[ROWS_PER_BLK][NC];
    int t = threadIdx.x;
    int r = t / NC;
    int k = t - r * NC;
    int lrow = blockIdx.x * ROWS_PER_BLK + r;

    if (r < ROWS_PER_BLK && lrow < GL) {
        float lam = (float)lrow * (1.0f / (GL - 1));
        float th = (k + 0.5f) * (PI_F / NC);
        float c  = C_MID + C_HALF * __cosf(th);
        float g0 = metric_eval(c,            lam, mW1, mb1, mW2, mb2, mW3, mb3);
        float gp = metric_eval(c + FD_EPS_F, lam, mW1, mb1, mW2, mb2, mW3, mb3);
        float gm = metric_eval(c - FD_EPS_F, lam, mW1, mb1, mW2, mb2, mW3, mb3);
        float dg = (gp - gm) * (1.0f / (2.0f * FD_EPS_F));
        nodes[r][k] = 0.5f * dg / g0;
    }
    __syncthreads();
    if (r < ROWS_PER_BLK && lrow < GL) {
        int j = k;
        float s = 0.0f;
#pragma unroll
        for (int q = 0; q < NC; q++)
            s += nodes[r][q] * __cosf((PI_F / NC) * (float)j * ((float)q + 0.5f));
        s *= (j == 0) ? (1.0f / NC) : (2.0f / NC);
        g_coef[lrow * NC + j] = s;
    }
}

// ----------------------------- main kernel ---------------------------------

// Even/odd split Clenshaw (two independent 4-term chains).
template<bool CLAMP>
__device__ __forceinline__ u64 eval_gamma_eo(const u64 co[NC], u64 C)
{
    u64 T;
    if (CLAMP) {
        float cx, cy; upk(C, cx, cy);
        cx = fminf(fmaxf(cx, C_MIN), C_MAX);
        cy = fminf(fmaxf(cy, C_MIN), C_MAX);
        T = pk(fmaf(cx, (float)C_INVH, (float)C_MOFF),
               fmaf(cy, (float)C_INVH, (float)C_MOFF));
    } else {
        T = pfma(C, PK_INVH, PK_MOFF);
    }
    u64 U  = pfma(padd(T, T), T, PK_M1);     // u = 2t^2 - 1
    u64 U2 = padd(U, U);

    const int H = NC / 2;   // 4 per chain
    u64 be1 = 0ull, be2 = 0ull;   // even chain (T-basis over u)
    u64 bo1 = 0ull, bo2 = 0ull;   // odd chain  (V-basis over u)
#pragma unroll
    for (int k = H - 1; k >= 1; k--) {
        u64 de = pfma(be2, PK_M1, co[2 * k]);
        u64 be = pfma(U2, be1, de);
        be2 = be1; be1 = be;
        u64 dd = pfma(bo2, PK_M1, co[2 * k + 1]);
        u64 bo = pfma(U2, bo1, dd);
        bo2 = bo1; bo1 = bo;
    }
    u64 pe = pfma(U, be1, pfma(be2, PK_M1, co[0]));       // e0 - be2 + u*be1
    u64 b0 = pfma(U2, bo1, pfma(bo2, PK_M1, co[1]));      // o0 + 2u*bo1 - bo2
    u64 dv = pfma(bo1, PK_M1, b0);                        // b0 - bo1
    return pfma(T, dv, pe);
}

// Euler c-endpoint: 9 full steps + 1 drift step (last Gamma is dead code).
__device__ __forceinline__ u64 integrate_c(const u64 co[NC], u64 C0, u64 V0)
{
    u64 C = C0, V = V0;
#pragma unroll 1
    for (int s = 0; s < 9; s++) {
        u64 G   = eval_gamma_eo<true>(co, C);
        u64 Cn  = pfma(V, PK_DT, C);
        u64 gv  = pmul(G, V);
        u64 gvv = pmul(gv, V);
        V = pfma(gvv, PK_NDT, V);
        C = Cn;
    }
    return pfma(V, PK_DT, C);
}

// All 10 reference shooting iterations in closed form from ONE integration.
__device__ __forceinline__ float shoot_single(float c0, float v0,
                                              float F0, float ctg)
{
    float Teff = __fdividef(F0 - c0, v0);
    float b    = 2.0f * Teff - 1.0f;
    bool ok    = (fabsf(v0) > 1e-7f) && (fabsf(b) > 0.1f);
    b = ok ? b : 1.0f;
    float vs = v0 + __fdividef(ctg - F0, b);
    float r  = 1.0f - 0.5f * b;
    float r2 = r * r, r4 = r2 * r2, r8 = r4 * r4, r10 = r8 * r2;
    return fmaf(r10, v0 - vs, vs);
}

__global__ __launch_bounds__(128, 5)
void geodesic_main_kernel(
    const float* __restrict__ c_src, const float* __restrict__ c_tgt,
    const float* __restrict__ lamv,  const float* __restrict__ A_src,
    const float* __restrict__ sW1,   const float* __restrict__ sb1,
    const float* __restrict__ sW2,   const float* __restrict__ sb2,
    float* __restrict__ out, int n)
{
    __shared__ ulonglong2 Wab[16];    // {pk(cw,cw), pk(vw,vw)}
    __shared__ ulonglong2 Wcd[16];    // {pk(aw,aw), (u64)f16x2(w2,w2)}
    __shared__ float shC[16], shB1[16];
    __shared__ float shT2;

    int t = threadIdx.x;
    if (t < 16) {
        int j = t;
        float a  = sW1[j];
        float b  = sW1[16 + j];
        float cw = sW1[32 + j];
        float dw = sW1[48 + j];
        float w2 = sW2[j];
        Wab[j] = make_ulonglong2(pk(a, a), pk(b, b));
        Wcd[j] = make_ulonglong2(pk(dw, dw), (u64)f2h2(w2));
        shC[j]  = cw;
        shB1[j] = sb1[j];
    } else if (t == 16) {
        shT2 = sb2[0];
    }
    __syncthreads();

    int half = (n + 1) >> 1;
    int i = blockIdx.x * 128 + t;
    if (i >= half) return;
    int i2 = i + half;
    bool has2 = (i2 < n);
    int j2 = has2 ? i2 : i;

    float c0x = c_src[i],  c0y = c_src[j2];
    float ctx = c_tgt[i],  cty = c_tgt[j2];
    float lmx = lamv[i],   lmy = lamv[j2];
    float a0x = A_src[i],  a0y = A_src[j2];

    // --- lambda-lerp of Chebyshev rows, packed (NC=8: 2 float4 per row) ---
    float yx = fminf(fmaxf(lmx * (float)(GL - 1), 0.0f), (float)(GL - 1));
    float yy = fminf(fmaxf(lmy * (float)(GL - 1), 0.0f), (float)(GL - 1));
    int lx = min((int)yx, GL - 2);
    int ly = min((int)yy, GL - 2);
    float fx = yx - (float)lx;
    float fy = yy - (float)ly;

    const float4* rx0 = (const float4*)(g_coef + lx * NC);
    const float4* rx1 = (const float4*)(g_coef + (lx + 1) * NC);
    const float4* ry0 = (const float4*)(g_coef + ly * NC);
    const float4* ry1 = (const float4*)(g_coef + (ly + 1) * NC);

    u64 co[NC];
#pragma unroll
    for (int q = 0; q < NC / 4; q++) {
        float4 ax = __ldg(rx0 + q), bx = __ldg(rx1 + q);
        float4 ay = __ldg(ry0 + q), by = __ldg(ry1 + q);
        co[4*q+0] = pk(fmaf(fx, bx.x - ax.x, ax.x), fmaf(fy, by.x - ay.x, ay.x));
        co[4*q+1] = pk(fmaf(fx, bx.y - ax.y, ax.y), fmaf(fy, by.y - ay.y, ay.y));
        co[4*q+2] = pk(fmaf(fx, bx.z - ax.z, ax.z), fmaf(fy, by.z - ay.z, ay.z));
        co[4*q+3] = pk(fmaf(fx, bx.w - ax.w, ax.w), fmaf(fy, by.w - ay.w, ay.w));
    }

    // --- per-element static flow terms S_j = b1_j + lam*W1c_j (registers) ---
    u64 S[16];
#pragma unroll
    for (int j = 0; j < 16; j++)
        S[j] = pk(fmaf(lmx, shC[j], shB1[j]), fmaf(lmy, shC[j], shB1[j]));

    // --- shooting: ONE truncated integration + derivative-model tail ---
    u64 C0p = pk(c0x, c0y);
    float v0x = ctx - c0x, v0y = cty - c0y;
    u64 F0p = integrate_c(co, C0p, pk(v0x, v0y));
    float F0x, F0y; upk(F0p, F0x, F0y);

    float vx = shoot_single(c0x, v0x, F0x, ctx);
    float vy = shoot_single(c0y, v0y, F0y, cty);

    // --- final integrate with spectral flow (no clamps: solved trajectory) ---
    u64 C = C0p, V = pk(vx, vy), A = pk(a0x, a0y);
    u64 T2p = pk(shT2, shT2);
#pragma unroll 1
    for (int s = 0; s < 10; s++) {
        u32 h0 = 0u, h1 = 0u, h2 = 0u, h3 = 0u;   // 4 indep f16x2 chains
#pragma unroll
        for (int j = 0; j < 16; j += 4) {
#pragma unroll
            for (int q = 0; q < 4; q++) {
                ulonglong2 wab = Wab[j + q];
                ulonglong2 wcd = Wcd[j + q];
                u64 pre = pfma(C, wab.x, S[j + q]);
                pre = pfma(V, wab.y, pre);
                pre = pfma(A, wcd.x, pre);
                u32 th = tanh_h2(cvt_h2(pre));
                u32 w2h = (u32)wcd.y;
                if (q == 0)      h0 = hfma2(th, w2h, h0);
                else if (q == 1) h1 = hfma2(th, w2h, h1);
                else if (q == 2) h2 = hfma2(th, w2h, h2);
                else             h3 = hfma2(th, w2h, h3);
            }
        }
        // combine chains in f16, ONE conversion to f32
        u32 hs = hadd2(hadd2(h0, h1), hadd2(h2, h3));
        u64 acc = padd(h2_to_p(hs), T2p);
        if (s < 9) {
            u64 G = eval_gamma_eo<false>(co, C);
            u64 Cn  = pfma(V, PK_DT, C);
            u64 gv  = pmul(G, V);
            u64 gvv = pmul(gv, V);
            V = pfma(gvv, PK_NDT, V);
            A = pfma(acc, PK_DT, A);
            C = Cn;
        } else {
            A = pfma(acc, PK_DT, A);   // last step: c/v updates are dead
        }
    }

    float Ax, Ay; upk(A, Ax, Ay);
    out[i] = Ax;
    if (has2) out[i2] = Ay;
}

// ----------------------------- launcher ------------------------------------

extern "C" void kernel_launch(void* const* d_in, const int* in_sizes, int n_in,
                              void* d_out, int out_size)
{
    const float* c_src = (const float*)d_in[0];
    const float* c_tgt = (const float*)d_in[1];
    const float* lam   = (const float*)d_in[2];
    const float* A_src = (const float*)d_in[3];
    const float* mW1 = (const float*)d_in[4];
    const float* mb1 = (const float*)d_in[5];
    const float* mW2 = (const float*)d_in[6];
    const float* mb2 = (const float*)d_in[7];
    const float* mW3 = (const float*)d_in[8];
    const float* mb3 = (const float*)d_in[9];
    const float* sW1 = (const float*)d_in[10];
    const float* sb1 = (const float*)d_in[11];
    const float* sW2 = (const float*)d_in[12];
    const float* sb2 = (const float*)d_in[13];

    int n = in_sizes[0];

    int pre_blocks = (GL + ROWS_PER_BLK - 1) / ROWS_PER_BLK;
    precompute_kernel<<<pre_blocks, ROWS_PER_BLK * NC>>>(mW1, mb1, mW2, mb2, mW3, mb3);

    int half = (n + 1) / 2;
    int blocks = (half + 127) / 128;
    geodesic_main_kernel<<<blocks, 128>>>(c_src, c_tgt, lam, A_src,
                                          sW1, sb1, sW2, sb2,
                                          (float*)d_out, n);
}